// round 1
// baseline (speedup 1.0000x reference)
#include <cuda_runtime.h>
#include <cstdint>
#include <cstddef>

// ---------------------------------------------------------------------------
// BitNet b1.58 fused MLP on GB300.
// x:[4096,4096] f32, w_gate/w_up:[11008,4096] f32, w_down:[4096,11008] f32
// All matmuls are EXACT int8 x ternary-int8 -> int32, with scalar dequant.
// ---------------------------------------------------------------------------

#define EPSF 1e-5f

constexpr int T_TOK = 4096;   // B*S = 2*2048
constexpr int HDIM  = 4096;
constexpr int IDIM  = 11008;
constexpr long WELEMS = (long)IDIM * HDIM;  // 45,088,768 (same for all 3 weights)

// ------------------------- device scratch ----------------------------------
__device__ __align__(128) int8_t d_wgq[WELEMS];
__device__ __align__(128) int8_t d_wuq[WELEMS];
__device__ __align__(128) int8_t d_wdq8[WELEMS];
__device__ __align__(128) int8_t d_xq[(long)T_TOK * HDIM];
__device__ __align__(128) int8_t d_hq[(long)T_TOK * IDIM];
__device__ __align__(128) float  d_gbuf[(long)T_TOK * IDIM];
__device__ __align__(128) float  d_ubuf[(long)T_TOK * IDIM];
__device__ float  d_xs[T_TOK];
__device__ float  d_hs[T_TOK];
__device__ double d_wsum[3];
__device__ float  d_wdeq[3];

// ------------------------- helpers -----------------------------------------
__device__ __forceinline__ void cp16(void* s, const void* g) {
    unsigned saddr = (unsigned)__cvta_generic_to_shared(s);
    asm volatile("cp.async.cg.shared.global [%0], [%1], 16;\n" :: "r"(saddr), "l"(g));
}
__device__ __forceinline__ void cp_commit() { asm volatile("cp.async.commit_group;\n"); }

__device__ __forceinline__ void mma_s8(int* c, const unsigned* a, const unsigned* b) {
    asm volatile(
        "mma.sync.aligned.m16n8k32.row.col.s32.s8.s8.s32 "
        "{%0,%1,%2,%3}, {%4,%5,%6,%7}, {%8,%9}, {%0,%1,%2,%3};\n"
        : "+r"(c[0]), "+r"(c[1]), "+r"(c[2]), "+r"(c[3])
        : "r"(a[0]), "r"(a[1]), "r"(a[2]), "r"(a[3]), "r"(b[0]), "r"(b[1]));
}

__device__ __forceinline__ float blockMaxF(float v, float* red) {
    #pragma unroll
    for (int o = 16; o > 0; o >>= 1)
        v = fmaxf(v, __shfl_down_sync(0xffffffffu, v, o));
    int wid = threadIdx.x >> 5;
    if ((threadIdx.x & 31) == 0) red[wid] = v;
    __syncthreads();
    if (threadIdx.x < 8) {
        v = red[threadIdx.x];
        #pragma unroll
        for (int o = 4; o > 0; o >>= 1)
            v = fmaxf(v, __shfl_down_sync(0xffu, v, o));
        if (threadIdx.x == 0) red[0] = v;
    }
    __syncthreads();
    return red[0];
}

// ------------------------- small kernels -----------------------------------
__global__ void zero_sums_kernel() {
    if (threadIdx.x < 3) d_wsum[threadIdx.x] = 0.0;
}

__global__ void absmean_kernel(const float* __restrict__ w, int idx) {
    const size_t n4 = (size_t)WELEMS / 4;
    const float4* w4 = (const float4*)w;
    double local = 0.0;
    for (size_t i = (size_t)blockIdx.x * blockDim.x + threadIdx.x; i < n4;
         i += (size_t)gridDim.x * blockDim.x) {
        float4 v = w4[i];
        local += (double)(fabsf(v.x) + fabsf(v.y) + fabsf(v.z) + fabsf(v.w));
    }
    // block reduce (double)
    #pragma unroll
    for (int o = 16; o > 0; o >>= 1)
        local += __shfl_down_sync(0xffffffffu, local, o);
    __shared__ double red[8];
    int wid = threadIdx.x >> 5;
    if ((threadIdx.x & 31) == 0) red[wid] = local;
    __syncthreads();
    if (threadIdx.x < 8) {
        local = red[threadIdx.x];
        #pragma unroll
        for (int o = 4; o > 0; o >>= 1)
            local += __shfl_down_sync(0xffu, local, o);
        if (threadIdx.x == 0) atomicAdd(&d_wsum[idx], local);
    }
}

__global__ void finalize_scales_kernel() {
    if (threadIdx.x == 0) {
        #pragma unroll
        for (int i = 0; i < 3; ++i) {
            double mean = d_wsum[i] / (double)WELEMS;
            d_wdeq[i] = (float)fmax(mean, (double)EPSF);  // dequant = clip(mean,eps)
        }
    }
}

__global__ void quantw_kernel(const float* __restrict__ w, int idx) {
    int8_t* q = (idx == 0) ? d_wgq : (idx == 1) ? d_wuq : d_wdq8;
    const float s = 1.0f / d_wdeq[idx];
    const size_t n4 = (size_t)WELEMS / 4;
    const float4* w4 = (const float4*)w;
    char4* q4 = (char4*)q;
    for (size_t i = (size_t)blockIdx.x * blockDim.x + threadIdx.x; i < n4;
         i += (size_t)gridDim.x * blockDim.x) {
        float4 v = w4[i];
        char4 c;
        c.x = (signed char)fminf(fmaxf(rintf(v.x * s), -1.f), 1.f);
        c.y = (signed char)fminf(fmaxf(rintf(v.y * s), -1.f), 1.f);
        c.z = (signed char)fminf(fmaxf(rintf(v.z * s), -1.f), 1.f);
        c.w = (signed char)fminf(fmaxf(rintf(v.w * s), -1.f), 1.f);
        q4[i] = c;
    }
}

__global__ void quantx_kernel(const float* __restrict__ x) {
    __shared__ float red[8];
    const int t = blockIdx.x;
    const float4* xr = (const float4*)(x + (size_t)t * HDIM);
    float4 v[4];
    float m = 0.f;
    #pragma unroll
    for (int j = 0; j < 4; ++j) {
        v[j] = xr[threadIdx.x + j * 256];
        m = fmaxf(m, fmaxf(fmaxf(fabsf(v[j].x), fabsf(v[j].y)),
                           fmaxf(fabsf(v[j].z), fabsf(v[j].w))));
    }
    float amax = blockMaxF(m, red);
    float cmax = fmaxf(amax, EPSF);
    float sc = 127.0f / cmax;
    if (threadIdx.x == 0) d_xs[t] = cmax / 127.0f;   // dequant factor
    char4* q4 = (char4*)(d_xq + (size_t)t * HDIM);
    #pragma unroll
    for (int j = 0; j < 4; ++j) {
        char4 c;
        c.x = (signed char)fminf(fmaxf(rintf(v[j].x * sc), -128.f), 127.f);
        c.y = (signed char)fminf(fmaxf(rintf(v[j].y * sc), -128.f), 127.f);
        c.z = (signed char)fminf(fmaxf(rintf(v[j].z * sc), -128.f), 127.f);
        c.w = (signed char)fminf(fmaxf(rintf(v[j].w * sc), -128.f), 127.f);
        q4[threadIdx.x + j * 256] = c;
    }
}

// h = relu(g)^2 * u, per-token absmax, quantize to int8
__global__ void combine_quanth_kernel() {
    __shared__ float sh[IDIM];   // 44032 B
    __shared__ float red[8];
    const int t = blockIdx.x;
    const float4* gr = (const float4*)(d_gbuf + (size_t)t * IDIM);
    const float4* ur = (const float4*)(d_ubuf + (size_t)t * IDIM);
    float4* sh4 = (float4*)sh;
    float m = 0.f;
    for (int i = threadIdx.x; i < IDIM / 4; i += 256) {
        float4 gv = gr[i], uv = ur[i], h;
        float r;
        r = fmaxf(gv.x, 0.f); h.x = r * r * uv.x;
        r = fmaxf(gv.y, 0.f); h.y = r * r * uv.y;
        r = fmaxf(gv.z, 0.f); h.z = r * r * uv.z;
        r = fmaxf(gv.w, 0.f); h.w = r * r * uv.w;
        sh4[i] = h;
        m = fmaxf(m, fmaxf(fmaxf(fabsf(h.x), fabsf(h.y)),
                           fmaxf(fabsf(h.z), fabsf(h.w))));
    }
    float amax = blockMaxF(m, red);
    float cmax = fmaxf(amax, EPSF);
    float sc = 127.0f / cmax;
    if (threadIdx.x == 0) d_hs[t] = cmax / 127.0f;
    __syncthreads();
    char4* q4 = (char4*)(d_hq + (size_t)t * IDIM);
    for (int i = threadIdx.x; i < IDIM / 4; i += 256) {
        float4 h = sh4[i];
        char4 c;
        c.x = (signed char)fminf(fmaxf(rintf(h.x * sc), -128.f), 127.f);
        c.y = (signed char)fminf(fmaxf(rintf(h.y * sc), -128.f), 127.f);
        c.z = (signed char)fminf(fmaxf(rintf(h.z * sc), -128.f), 127.f);
        c.w = (signed char)fminf(fmaxf(rintf(h.w * sc), -128.f), 127.f);
        q4[i] = c;
    }
}

// ------------------------- int8 GEMM ---------------------------------------
// C[M=4096, NDIM] = A[M, KDIM] (s8, row-major) x B[NDIM, KDIM]^T (s8)
// MODE 0: A=d_xq, B = wg/wu per blockIdx.z, out = d_gbuf/d_ubuf (dequant fp32)
// MODE 1: A=d_hq, B = d_wdq8, out = out_arg (d_out)
template <int NDIM, int KDIM, int MODE>
__global__ __launch_bounds__(256) void gemm_s8_kernel(float* __restrict__ out_arg) {
    constexpr int BM = 128, BN = 128, BK = 64, STRIDE = 80;
    __shared__ int8_t sA[2][BM * STRIDE];
    __shared__ int8_t sB[2][BN * STRIDE];

    const int8_t* A;
    const int8_t* Bm;
    float* outp;
    const float* ascale;
    float wsc;
    if (MODE == 0) {
        A = d_xq; ascale = d_xs;
        if (blockIdx.z == 0) { Bm = d_wgq; outp = d_gbuf; wsc = d_wdeq[0]; }
        else                 { Bm = d_wuq; outp = d_ubuf; wsc = d_wdeq[1]; }
    } else {
        A = d_hq; ascale = d_hs; Bm = d_wdq8; outp = out_arg; wsc = d_wdeq[2];
    }

    const int tid = threadIdx.x;
    const int m0 = blockIdx.y * BM, n0 = blockIdx.x * BN;
    const int wid = tid >> 5, lane = tid & 31;
    const int wm = (wid & 1) * 64, wn = (wid >> 1) * 32;
    const int g = lane >> 2, tg = lane & 3;

    int acc[4][4][4];
    #pragma unroll
    for (int mi = 0; mi < 4; ++mi)
        #pragma unroll
        for (int ni = 0; ni < 4; ++ni)
            #pragma unroll
            for (int k = 0; k < 4; ++k) acc[mi][ni][k] = 0;

    auto load_tile = [&](int kt, int buf) {
        const int k0 = kt * BK;
        #pragma unroll
        for (int j = 0; j < 2; ++j) {
            int cid = tid + j * 256;           // 0..511
            int row = cid >> 2, col = (cid & 3) * 16;
            cp16(&sA[buf][row * STRIDE + col],
                 A + (size_t)(m0 + row) * KDIM + k0 + col);
            cp16(&sB[buf][row * STRIDE + col],
                 Bm + (size_t)(n0 + row) * KDIM + k0 + col);
        }
    };

    constexpr int KT = KDIM / BK;
    load_tile(0, 0);
    cp_commit();

    for (int kt = 0; kt < KT; ++kt) {
        if (kt + 1 < KT) {
            load_tile(kt + 1, (kt + 1) & 1);
            cp_commit();
            asm volatile("cp.async.wait_group 1;\n");
        } else {
            asm volatile("cp.async.wait_group 0;\n");
        }
        __syncthreads();
        const int8_t* As = sA[kt & 1];
        const int8_t* Bs = sB[kt & 1];
        #pragma unroll
        for (int kk = 0; kk < 2; ++kk) {
            const int ko = kk * 32;
            unsigned a[4][4], b[4][2];
            #pragma unroll
            for (int mi = 0; mi < 4; ++mi) {
                int r = wm + mi * 16 + g;
                a[mi][0] = *(const unsigned*)(As + r * STRIDE + ko + tg * 4);
                a[mi][1] = *(const unsigned*)(As + (r + 8) * STRIDE + ko + tg * 4);
                a[mi][2] = *(const unsigned*)(As + r * STRIDE + ko + 16 + tg * 4);
                a[mi][3] = *(const unsigned*)(As + (r + 8) * STRIDE + ko + 16 + tg * 4);
            }
            #pragma unroll
            for (int ni = 0; ni < 4; ++ni) {
                int c = wn + ni * 8 + g;
                b[ni][0] = *(const unsigned*)(Bs + c * STRIDE + ko + tg * 4);
                b[ni][1] = *(const unsigned*)(Bs + c * STRIDE + ko + 16 + tg * 4);
            }
            #pragma unroll
            for (int mi = 0; mi < 4; ++mi)
                #pragma unroll
                for (int ni = 0; ni < 4; ++ni)
                    mma_s8(acc[mi][ni], a[mi], b[ni]);
        }
        __syncthreads();
    }

    // epilogue: dequant + store
    #pragma unroll
    for (int mi = 0; mi < 4; ++mi) {
        int r0 = m0 + wm + mi * 16 + g;
        int r1 = r0 + 8;
        float s0 = ascale[r0] * wsc;
        float s1 = ascale[r1] * wsc;
        #pragma unroll
        for (int ni = 0; ni < 4; ++ni) {
            int c = n0 + wn + ni * 8 + tg * 2;
            float2 v0 = make_float2(acc[mi][ni][0] * s0, acc[mi][ni][1] * s0);
            float2 v1 = make_float2(acc[mi][ni][2] * s1, acc[mi][ni][3] * s1);
            *(float2*)(outp + (size_t)r0 * NDIM + c) = v0;
            *(float2*)(outp + (size_t)r1 * NDIM + c) = v1;
        }
    }
}

// ------------------------- launch ------------------------------------------
extern "C" void kernel_launch(void* const* d_in, const int* in_sizes, int n_in,
                              void* d_out, int out_size) {
    const float* x      = (const float*)d_in[0];
    const float* w_gate = (const float*)d_in[1];
    const float* w_up   = (const float*)d_in[2];
    const float* w_down = (const float*)d_in[3];
    float* out = (float*)d_out;

    zero_sums_kernel<<<1, 32>>>();

    absmean_kernel<<<1184, 256>>>(w_gate, 0);
    absmean_kernel<<<1184, 256>>>(w_up, 1);
    absmean_kernel<<<1184, 256>>>(w_down, 2);

    finalize_scales_kernel<<<1, 32>>>();

    quantw_kernel<<<1184, 256>>>(w_gate, 0);
    quantw_kernel<<<1184, 256>>>(w_up, 1);
    quantw_kernel<<<1184, 256>>>(w_down, 2);

    quantx_kernel<<<T_TOK, 256>>>(x);

    // gate + up GEMMs (grid.z selects weight), fused dequant epilogue
    gemm_s8_kernel<IDIM, HDIM, 0><<<dim3(IDIM / 128, T_TOK / 128, 2), 256>>>(nullptr);

    combine_quanth_kernel<<<T_TOK, 256>>>();

    // down GEMM -> output
    gemm_s8_kernel<HDIM, IDIM, 1><<<dim3(HDIM / 128, T_TOK / 128, 1), 256>>>(out);
}

// round 4
// speedup vs baseline: 1.0350x; 1.0350x over previous
#include <cuda_runtime.h>
#include <cstdint>
#include <cstddef>

// ---------------------------------------------------------------------------
// BitNet b1.58 fused MLP on GB300 (sm_103 target -> mma.sync IMMA path).
//   x:[4096,4096] f32, w_gate/w_up:[11008,4096] f32, w_down:[4096,11008] f32
//   All matmuls are EXACT int8 x ternary-int8 -> s32.
// ---------------------------------------------------------------------------

#define EPSF 1e-5f

constexpr int T_TOK = 4096;   // B*S
constexpr int HDIM  = 4096;
constexpr int IDIM  = 11008;
constexpr long WELEMS = (long)IDIM * HDIM;

// ------------------------- device scratch ----------------------------------
__device__ __align__(128) int8_t d_wgq[WELEMS];
__device__ __align__(128) int8_t d_wuq[WELEMS];
__device__ __align__(128) int8_t d_wdq8[WELEMS];
__device__ __align__(128) int8_t d_xq[(long)T_TOK * HDIM];
__device__ __align__(128) int8_t d_hq[(long)T_TOK * IDIM];
__device__ __align__(128) float  d_gbuf[(long)T_TOK * IDIM];
__device__ __align__(128) float  d_ubuf[(long)T_TOK * IDIM];
__device__ float  d_xs[T_TOK];
__device__ float  d_hs[T_TOK];
__device__ double d_wsum[3];
__device__ float  d_wdeq[3];

// ------------------------- helpers -----------------------------------------
__device__ __forceinline__ unsigned smem_u32(const void* p) {
    return (unsigned)__cvta_generic_to_shared(p);
}
// 64B-row swizzle: seg bits[5:4] ^= row bits (row&6)>>1 — conflict-free for
// both cp.async 16B stores and ldmatrix 16B reads.
__device__ __forceinline__ unsigned swz64(unsigned off) {
    return off ^ ((off >> 3) & 0x30);
}
__device__ __forceinline__ void cp16(unsigned saddr, const void* g) {
    asm volatile("cp.async.cg.shared.global [%0], [%1], 16;\n" :: "r"(saddr), "l"(g));
}
__device__ __forceinline__ void ldsm4(unsigned* r, unsigned addr) {
    asm volatile("ldmatrix.sync.aligned.m8n8.x4.shared.b16 {%0,%1,%2,%3}, [%4];"
                 : "=r"(r[0]), "=r"(r[1]), "=r"(r[2]), "=r"(r[3]) : "r"(addr));
}
__device__ __forceinline__ void mma_s8(int* c, const unsigned* a, const unsigned* b) {
    asm volatile(
        "mma.sync.aligned.m16n8k32.row.col.s32.s8.s8.s32 "
        "{%0,%1,%2,%3}, {%4,%5,%6,%7}, {%8,%9}, {%0,%1,%2,%3};\n"
        : "+r"(c[0]), "+r"(c[1]), "+r"(c[2]), "+r"(c[3])
        : "r"(a[0]), "r"(a[1]), "r"(a[2]), "r"(a[3]), "r"(b[0]), "r"(b[1]));
}

__device__ __forceinline__ float blockMaxF(float v, float* red) {
    #pragma unroll
    for (int o = 16; o > 0; o >>= 1)
        v = fmaxf(v, __shfl_down_sync(0xffffffffu, v, o));
    int wid = threadIdx.x >> 5;
    if ((threadIdx.x & 31) == 0) red[wid] = v;
    __syncthreads();
    if (threadIdx.x < 8) {
        v = red[threadIdx.x];
        #pragma unroll
        for (int o = 4; o > 0; o >>= 1)
            v = fmaxf(v, __shfl_down_sync(0xffu, v, o));
        if (threadIdx.x == 0) red[0] = v;
    }
    __syncthreads();
    return red[0];
}

// ------------------------- small kernels -----------------------------------
__global__ void zero_sums_kernel() {
    if (threadIdx.x < 3) d_wsum[threadIdx.x] = 0.0;
}

__global__ void absmean3_kernel(const float* __restrict__ w0,
                                const float* __restrict__ w1,
                                const float* __restrict__ w2) {
    const int idx = blockIdx.z;
    const float* w = (idx == 0) ? w0 : (idx == 1) ? w1 : w2;
    const size_t n4 = (size_t)WELEMS / 4;
    const float4* w4 = (const float4*)w;
    float a0 = 0.f, a1 = 0.f, a2 = 0.f, a3 = 0.f;
    for (size_t i = (size_t)blockIdx.x * blockDim.x + threadIdx.x; i < n4;
         i += (size_t)gridDim.x * blockDim.x) {
        float4 v = w4[i];
        a0 += fabsf(v.x); a1 += fabsf(v.y); a2 += fabsf(v.z); a3 += fabsf(v.w);
    }
    double local = ((double)a0 + (double)a1) + ((double)a2 + (double)a3);
    #pragma unroll
    for (int o = 16; o > 0; o >>= 1)
        local += __shfl_down_sync(0xffffffffu, local, o);
    __shared__ double red[8];
    int wid = threadIdx.x >> 5;
    if ((threadIdx.x & 31) == 0) red[wid] = local;
    __syncthreads();
    if (threadIdx.x < 8) {
        local = red[threadIdx.x];
        #pragma unroll
        for (int o = 4; o > 0; o >>= 1)
            local += __shfl_down_sync(0xffu, local, o);
        if (threadIdx.x == 0) atomicAdd(&d_wsum[idx], local);
    }
}

__global__ void finalize_scales_kernel() {
    if (threadIdx.x == 0) {
        #pragma unroll
        for (int i = 0; i < 3; ++i) {
            double mean = d_wsum[i] / (double)WELEMS;
            d_wdeq[i] = (float)fmax(mean, (double)EPSF);
        }
    }
}

__global__ void quantw3_kernel(const float* __restrict__ w0,
                               const float* __restrict__ w1,
                               const float* __restrict__ w2) {
    const int idx = blockIdx.z;
    const float* w = (idx == 0) ? w0 : (idx == 1) ? w1 : w2;
    int8_t* q = (idx == 0) ? d_wgq : (idx == 1) ? d_wuq : d_wdq8;
    const float s = 1.0f / d_wdeq[idx];
    const size_t n4 = (size_t)WELEMS / 4;
    const float4* w4 = (const float4*)w;
    char4* q4 = (char4*)q;
    for (size_t i = (size_t)blockIdx.x * blockDim.x + threadIdx.x; i < n4;
         i += (size_t)gridDim.x * blockDim.x) {
        float4 v = w4[i];
        char4 c;
        c.x = (signed char)fminf(fmaxf(rintf(v.x * s), -1.f), 1.f);
        c.y = (signed char)fminf(fmaxf(rintf(v.y * s), -1.f), 1.f);
        c.z = (signed char)fminf(fmaxf(rintf(v.z * s), -1.f), 1.f);
        c.w = (signed char)fminf(fmaxf(rintf(v.w * s), -1.f), 1.f);
        q4[i] = c;
    }
}

__global__ void quantx_kernel(const float* __restrict__ x) {
    __shared__ float red[8];
    const int t = blockIdx.x;
    const float4* xr = (const float4*)(x + (size_t)t * HDIM);
    float4 v[4];
    float m = 0.f;
    #pragma unroll
    for (int j = 0; j < 4; ++j) {
        v[j] = xr[threadIdx.x + j * 256];
        m = fmaxf(m, fmaxf(fmaxf(fabsf(v[j].x), fabsf(v[j].y)),
                           fmaxf(fabsf(v[j].z), fabsf(v[j].w))));
    }
    float amax = blockMaxF(m, red);
    float cmax = fmaxf(amax, EPSF);
    float sc = 127.0f / cmax;
    if (threadIdx.x == 0) d_xs[t] = cmax / 127.0f;
    char4* q4 = (char4*)(d_xq + (size_t)t * HDIM);
    #pragma unroll
    for (int j = 0; j < 4; ++j) {
        char4 c;
        c.x = (signed char)fminf(fmaxf(rintf(v[j].x * sc), -128.f), 127.f);
        c.y = (signed char)fminf(fmaxf(rintf(v[j].y * sc), -128.f), 127.f);
        c.z = (signed char)fminf(fmaxf(rintf(v[j].z * sc), -128.f), 127.f);
        c.w = (signed char)fminf(fmaxf(rintf(v[j].w * sc), -128.f), 127.f);
        q4[threadIdx.x + j * 256] = c;
    }
}

// h = relu(g)^2 * u, per-token absmax, quantize to int8
__global__ void combine_quanth_kernel() {
    __shared__ float sh[IDIM];
    __shared__ float red[8];
    const int t = blockIdx.x;
    const float4* gr = (const float4*)(d_gbuf + (size_t)t * IDIM);
    const float4* ur = (const float4*)(d_ubuf + (size_t)t * IDIM);
    float4* sh4 = (float4*)sh;
    float m = 0.f;
    for (int i = threadIdx.x; i < IDIM / 4; i += 256) {
        float4 gv = gr[i], uv = ur[i], h;
        float r;
        r = fmaxf(gv.x, 0.f); h.x = r * r * uv.x;
        r = fmaxf(gv.y, 0.f); h.y = r * r * uv.y;
        r = fmaxf(gv.z, 0.f); h.z = r * r * uv.z;
        r = fmaxf(gv.w, 0.f); h.w = r * r * uv.w;
        sh4[i] = h;
        m = fmaxf(m, fmaxf(fmaxf(fabsf(h.x), fabsf(h.y)),
                           fmaxf(fabsf(h.z), fabsf(h.w))));
    }
    float amax = blockMaxF(m, red);
    float cmax = fmaxf(amax, EPSF);
    float sc = 127.0f / cmax;
    if (threadIdx.x == 0) d_hs[t] = cmax / 127.0f;
    __syncthreads();
    char4* q4 = (char4*)(d_hq + (size_t)t * IDIM);
    for (int i = threadIdx.x; i < IDIM / 4; i += 256) {
        float4 h = sh4[i];
        char4 c;
        c.x = (signed char)fminf(fmaxf(rintf(h.x * sc), -128.f), 127.f);
        c.y = (signed char)fminf(fmaxf(rintf(h.y * sc), -128.f), 127.f);
        c.z = (signed char)fminf(fmaxf(rintf(h.z * sc), -128.f), 127.f);
        c.w = (signed char)fminf(fmaxf(rintf(h.w * sc), -128.f), 127.f);
        q4[i] = c;
    }
}

// ------------------------- int8 GEMM (IMMA + ldmatrix + 4-stage) -----------
// C[M=4096, NDIM] = A[M, KDIM] (s8, row-major K) x B[NDIM, KDIM]^T (s8)
// MODE 0: A=d_xq, B = wg/wu per blockIdx.z, out = d_gbuf/d_ubuf (dequant fp32)
// MODE 1: A=d_hq, B = d_wdq8, out = out_arg (d_out)
template <int NDIM, int KDIM, int MODE>
__global__ __launch_bounds__(256, 2) void gemm_s8_kernel(float* __restrict__ out_arg) {
    constexpr int BM = 128, BN = 128, BK = 64;
    constexpr int STAGE_B = 16384;            // A 8KB + B 8KB per stage
    constexpr int KT = KDIM / BK;
    extern __shared__ int8_t smem[];
    const unsigned sbase = smem_u32(smem);

    const int8_t* A;
    const int8_t* Bm;
    float* outp;
    const float* ascale;
    const float* wdq;
    int wsel;
    if (MODE == 0) {
        A = d_xq; ascale = d_xs;
        if (blockIdx.z == 0) { Bm = d_wgq; outp = d_gbuf; wsel = 0; }
        else                 { Bm = d_wuq; outp = d_ubuf; wsel = 1; }
    } else {
        A = d_hq; ascale = d_hs; Bm = d_wdq8; outp = out_arg; wsel = 2;
    }

    const int tid = threadIdx.x;
    const int m0 = blockIdx.y * BM, n0 = blockIdx.x * BN;
    const int wid = tid >> 5, lane = tid & 31;
    const int wm = (wid & 1) * 64, wn = (wid >> 1) * 32;

    // ldmatrix per-lane address templates (see fragment-mapping analysis)
    const int arow = (lane & 7) + ((lane >> 3) & 1) * 8;   // + row base
    const int aks  = (lane >> 4) * 16;                      // k byte offset
    const int brow = (lane & 7) + ((lane >> 4) & 1) * 8;
    const int bks  = ((lane >> 3) & 1) * 16;

    int acc[4][4][4];
    #pragma unroll
    for (int mi = 0; mi < 4; ++mi)
        #pragma unroll
        for (int ni = 0; ni < 4; ++ni)
            #pragma unroll
            for (int k = 0; k < 4; ++k) acc[mi][ni][k] = 0;

    auto load_stage = [&](int kt) {
        if (kt < KT) {
            const unsigned sS = sbase + (kt & 3) * STAGE_B;
            const int k0 = kt * BK;
            #pragma unroll
            for (int i = 0; i < 2; ++i) {          // A: 128 rows x 4 segs
                int u = tid + i * 256;
                cp16(sS + swz64((u >> 2) * 64 + (u & 3) * 16),
                     A + (size_t)(m0 + (u >> 2)) * KDIM + k0 + (u & 3) * 16);
            }
            #pragma unroll
            for (int i = 0; i < 2; ++i) {          // B: 128 rows x 4 segs
                int u = tid + i * 256;
                cp16(sS + 8192 + swz64((u >> 2) * 64 + (u & 3) * 16),
                     Bm + (size_t)(n0 + (u >> 2)) * KDIM + k0 + (u & 3) * 16);
            }
        }
        asm volatile("cp.async.commit_group;\n");
    };

    load_stage(0); load_stage(1); load_stage(2);

    for (int kt = 0; kt < KT; ++kt) {
        asm volatile("cp.async.wait_group 2;\n");
        __syncthreads();
        const unsigned sA = sbase + (kt & 3) * STAGE_B;
        const unsigned sB = sA + 8192;
        #pragma unroll
        for (int kk = 0; kk < BK; kk += 32) {
            unsigned a[4][4], b[2][4];
            #pragma unroll
            for (int mi = 0; mi < 4; ++mi)
                ldsm4(a[mi], sA + swz64((wm + mi * 16 + arow) * 64 + kk + aks));
            #pragma unroll
            for (int np = 0; np < 2; ++np)
                ldsm4(b[np], sB + swz64((wn + np * 16 + brow) * 64 + kk + bks));
            #pragma unroll
            for (int mi = 0; mi < 4; ++mi)
                #pragma unroll
                for (int ni = 0; ni < 4; ++ni)
                    mma_s8(acc[mi][ni], a[mi], &b[ni >> 1][(ni & 1) * 2]);
        }
        load_stage(kt + 3);
    }

    // epilogue: dequant + store
    const float wsc = d_wdeq[wsel];
    const int g = lane >> 2, tg = lane & 3;
    #pragma unroll
    for (int mi = 0; mi < 4; ++mi) {
        int r0 = m0 + wm + mi * 16 + g;
        int r1 = r0 + 8;
        float s0 = ascale[r0] * wsc;
        float s1 = ascale[r1] * wsc;
        #pragma unroll
        for (int ni = 0; ni < 4; ++ni) {
            int c = n0 + wn + ni * 8 + tg * 2;
            float2 v0 = make_float2(acc[mi][ni][0] * s0, acc[mi][ni][1] * s0);
            float2 v1 = make_float2(acc[mi][ni][2] * s1, acc[mi][ni][3] * s1);
            *(float2*)(outp + (size_t)r0 * NDIM + c) = v0;
            *(float2*)(outp + (size_t)r1 * NDIM + c) = v1;
        }
    }
}

// ------------------------- launch ------------------------------------------
extern "C" void kernel_launch(void* const* d_in, const int* in_sizes, int n_in,
                              void* d_out, int out_size) {
    const float* x      = (const float*)d_in[0];
    const float* w_gate = (const float*)d_in[1];
    const float* w_up   = (const float*)d_in[2];
    const float* w_down = (const float*)d_in[3];
    float* out = (float*)d_out;

    constexpr int GSMEM = 4 * 16384;   // 65536 B dynamic

    cudaFuncSetAttribute(gemm_s8_kernel<IDIM, HDIM, 0>,
                         cudaFuncAttributeMaxDynamicSharedMemorySize, GSMEM);
    cudaFuncSetAttribute(gemm_s8_kernel<HDIM, IDIM, 1>,
                         cudaFuncAttributeMaxDynamicSharedMemorySize, GSMEM);

    zero_sums_kernel<<<1, 32>>>();

    absmean3_kernel<<<dim3(592, 1, 3), 256>>>(w_gate, w_up, w_down);

    finalize_scales_kernel<<<1, 32>>>();

    quantw3_kernel<<<dim3(592, 1, 3), 256>>>(w_gate, w_up, w_down);

    quantx_kernel<<<T_TOK, 256>>>(x);

    // gate + up GEMMs (grid.z selects weight), fused dequant epilogue
    gemm_s8_kernel<IDIM, HDIM, 0>
        <<<dim3(IDIM / 128, T_TOK / 128, 2), 256, GSMEM>>>(nullptr);

    combine_quanth_kernel<<<T_TOK, 256>>>();

    // down GEMM -> output
    gemm_s8_kernel<HDIM, IDIM, 1>
        <<<dim3(HDIM / 128, T_TOK / 128, 1), 256, GSMEM>>>(out);
}